// round 7
// baseline (speedup 1.0000x reference)
#include <cuda_runtime.h>
#include <cstdint>
#include <cstddef>

// CTC batch cost (keras ctc_batch_cost), prob-domain forward, exact biased
// power-of-2 rescaling, cp.async.bulk streaming + L2 prefetch ~8 quarters
// ahead. 96KB ring = 6 x 16KB quarters. One warp per batch element.
static constexpr int Bn = 256, Tn = 512, Cn = 256, Un = 64;
static constexpr int BLANK = Cn - 1;
static constexpr float EPSF = 1e-7f;
static constexpr float Kc = 256.f;      // exact power of 2
static constexpr float EK = 256.f * EPSF;
static constexpr int   BIAS = 48;       // pins working level ~2^48: no FTZ
static constexpr int   NSLOT = 6;
static constexpr int   SMEM_TOTAL = NSLOT * 16384;   // 96KB

__device__ __forceinline__ void mwait(uint32_t mbar, uint32_t parity) {
    asm volatile(
        "{\n\t.reg .pred P;\n"
        "WL_%=:\n\t"
        "mbarrier.try_wait.parity.acquire.cta.shared::cta.b64 P, [%0], %1, 0x989680;\n\t"
        "@P bra WD_%=;\n\t"
        "bra WL_%=;\n"
        "WD_%=:\n\t}"
        :: "r"(mbar), "r"(parity) : "memory");
}

// lane 0 (predicated): expect_tx + 16KB bulk copy gmem->smem
__device__ __forceinline__ void bulk_fill(uint32_t mbar, uint32_t sdst,
                                          const float* gsrc, int lane) {
    asm volatile(
        "{\n\t.reg .pred P;\n\t"
        "setp.eq.s32 P, %3, 0;\n\t"
        "@P mbarrier.arrive.expect_tx.shared.b64 _, [%0], 16384;\n\t"
        "@P cp.async.bulk.shared::cta.global.mbarrier::complete_tx::bytes [%1], [%2], 16384, [%0];\n\t"
        "}"
        :: "r"(mbar), "r"(sdst), "l"(gsrc), "r"(lane) : "memory");
}

// lane 0 (predicated): fire-and-forget 16KB L2 prefetch
__device__ __forceinline__ void bulk_prefetch(const float* gsrc, int lane) {
    asm volatile(
        "{\n\t.reg .pred P;\n\t"
        "setp.eq.s32 P, %1, 0;\n\t"
        "@P cp.async.bulk.prefetch.L2.global [%0], 16384;\n\t"
        "}"
        :: "l"(gsrc), "r"(lane) : "memory");
}

// Lane L owns states 4L..4L+3; a4 = state 128 on lane 31 only (0 elsewhere).
__device__ __forceinline__ void dp_step(float& a0, float& a1, float& a2,
                                        float& a3, float& a4,
                                        float vB, float v0, float v1,
                                        float sk1, float sk3, int lane) {
    float pa3 = __shfl_up_sync(0xffffffffu, a3, 1);
    if (lane == 0) pa3 = 0.f;
    float na0 = (a0 + pa3) * vB;
    float na1 = fmaf(sk1, pa3, a0 + a1) * v0;
    float na2 = (a1 + a2) * vB;
    float na3 = fmaf(sk3, a1, a2 + a3) * v1;
    float na4 = (lane == 31) ? (a3 + a4) * vB : 0.f;
    a0 = na0; a1 = na1; a2 = na2; a3 = na3; a4 = na4;
}

#define LOADV(SLOT)                                                          \
    { _Pragma("unroll") for (int i_ = 0; i_ < 4; i_++) {                     \
        vB[i_] = fmaf(pB[((SLOT) + i_) * Cn], Kc, EK);                       \
        v0[i_] = fmaf(p0[((SLOT) + i_) * Cn], Kc, EK);                       \
        v1[i_] = fmaf(p1[((SLOT) + i_) * Cn], Kc, EK); } }

#define APPLY()                                                              \
    { uint32_t bb_ = __float_as_uint(bf);                                    \
      int sh_ = (int)(bb_ >> 23) - 127 - BIAS;                               \
      if (sh_ < -120) sh_ = -120;                                            \
      E += sh_;                                                              \
      float r_ = __uint_as_float((uint32_t)(127 - sh_) << 23);               \
      a0 *= r_; a1 *= r_; a2 *= r_; a3 *= r_; a4 *= r_; }

#define DPS(i_) dp_step(a0,a1,a2,a3,a4, vB[i_],v0[i_],v1[i_], sk1,sk3, lane)

#define GRPA(SLOT)                                                           \
    { float vB[4], v0[4], v1[4]; LOADV(SLOT); APPLY();                       \
      DPS(0); DPS(1); DPS(2); DPS(3);                                        \
      ls = ((a0 + a1) + (a2 + a3)) + a4;                                     \
      ls += __shfl_xor_sync(0xffffffffu, ls, 16); }

#define GRPB(SLOT)                                                           \
    { float vB[4], v0[4], v1[4]; LOADV(SLOT);                                \
      DPS(0); ls += __shfl_xor_sync(0xffffffffu, ls, 8);                     \
      DPS(1); ls += __shfl_xor_sync(0xffffffffu, ls, 4);                     \
      DPS(2); ls += __shfl_xor_sync(0xffffffffu, ls, 2);                     \
      DPS(3); ls += __shfl_xor_sync(0xffffffffu, ls, 1);                     \
      bf = ls; }

// quarter q at ring slot SL: refill + prefetch issued BEFORE the wait (they
// depend only on already-consumed quarters), then wait, then 16 dp steps.
#define QBLK(SL, PAR, RSL, OK, PF)                                           \
    { if (OK) { bulk_fill(mbase + 8u * (RSL), sbase + (RSL) * 16384u, gR, lane); \
                gR += 4096; }                                                \
      if (PF) { bulk_prefetch(gP, lane); gP += 4096; }                       \
      mwait(mbase + 8u * (SL), (PAR)); __syncwarp();                         \
      GRPB(16 * (SL)); GRPA(16 * (SL) + 4);                                  \
      GRPB(16 * (SL) + 8); GRPA(16 * (SL) + 12); }

__global__ void ctc_fwd_kernel(const int* __restrict__ y_true,
                               const float* __restrict__ y_pred,
                               float* __restrict__ out) {
    extern __shared__ float stg[];                 // 96 rows x 256 f32
    __shared__ __align__(8) unsigned long long mb[NSLOT];
    const int b = blockIdx.x, lane = threadIdx.x;
    const float* g = y_pred + (size_t)b * Tn * Cn;
    const uint32_t sbase = (uint32_t)__cvta_generic_to_shared(stg);
    const uint32_t mbase = (uint32_t)__cvta_generic_to_shared(mb);

    if (lane == 0) {
#pragma unroll
        for (int q = 0; q < NSLOT; q++)
            asm volatile("mbarrier.init.shared.b64 [%0], 1;" :: "r"(mbase + 8u * q) : "memory");
        asm volatile("fence.proxy.async.shared::cta;" ::: "memory");
    }
    __syncwarp();
#pragma unroll
    for (int q = 0; q < NSLOT; q++)                // fills: quarters 0..5
        bulk_fill(mbase + 8u * q, sbase + q * 16384u, g + q * 4096, lane);
#pragma unroll
    for (int q = NSLOT; q < NSLOT + 8; q++)        // L2 prefetch: quarters 6..13
        bulk_prefetch(g + q * 4096, lane);

    const int l0 = y_true[b * Un + 2 * lane];
    const int l1 = y_true[b * Un + 2 * lane + 1];
    const int lp = __shfl_up_sync(0xffffffffu, l1, 1);
    const float sk1 = (lane == 0) ? 0.f : ((l0 != lp) ? 1.f : 0.f);
    const float sk3 = (l1 != l0) ? 1.f : 0.f;

    const float* pB = stg + BLANK;
    const float* p0 = stg + l0;
    const float* p1 = stg + l1;

    // ---- quarter 0 (slot 0, parity 0): t=0 init + t=1..3 peel + A B A
    mwait(mbase, 0u);
    __syncwarp();
    float a0 = 0.f, a1 = 0.f, a2 = 0.f, a3 = 0.f, a4 = 0.f;
    if (lane == 0) { a0 = pB[0] + EPSF; a1 = p0[0] + EPSF; }
#pragma unroll
    for (int t = 1; t < 4; t++) {
        float vB = fmaf(pB[t * Cn], Kc, EK);
        float v0 = fmaf(p0[t * Cn], Kc, EK);
        float v1 = fmaf(p1[t * Cn], Kc, EK);
        dp_step(a0, a1, a2, a3, a4, vB, v0, v1, sk1, sk3, lane);
    }
    float ls = 0.f, bf = 1.f;
    int   E  = 0;
    const float* gR = g + NSLOT * 4096;            // next fill quarter: 6
    const float* gP = g + (NSLOT + 8) * 4096;      // next prefetch quarter: 14

    GRPA(4); GRPB(8); GRPA(12);

    // ---- quarters 1..30: i=0..4, positions k=1..6 (q = 6i+k)
    // fills for q<=26 (targets 11..31); prefetch for q<=18 (targets 14..31)
#pragma unroll 1
    for (int i = 0; i < 5; i++) {
        const uint32_t pe = (uint32_t)(i & 1), po = pe ^ 1u;
        const int q6 = 6 * i;
        QBLK(1, pe, 0, (q6 + 1) <= 26, (q6 + 1) <= 18);
        QBLK(2, pe, 1, (q6 + 2) <= 26, (q6 + 2) <= 18);
        QBLK(3, pe, 2, (q6 + 3) <= 26, (q6 + 3) <= 18);
        QBLK(4, pe, 3, (q6 + 4) <= 26, (q6 + 4) <= 18);
        QBLK(5, pe, 4, (q6 + 5) <= 26, (q6 + 5) <= 18);
        QBLK(0, po, 5, (q6 + 6) <= 26, (q6 + 6) <= 18);
    }
    // ---- quarter 31 (slot 1, parity 1), no refill/prefetch
    QBLK(1, 1u, 0, false, false);

    // stored tail = true_tail * 256^511 * 2^-E (E exactly bookkept)
    if (lane == 31) {
        const float LN2 = 0.69314718055994530942f;
        out[b] = -(logf(a3 + a4) + (float)(E - 4088) * LN2);
    }
}

extern "C" void kernel_launch(void* const* d_in, const int* in_sizes, int n_in,
                              void* d_out, int out_size) {
    const int* y_true;
    const float* y_pred;
    if (in_sizes[0] == Bn * Un) {
        y_true = (const int*)d_in[0];
        y_pred = (const float*)d_in[1];
    } else {
        y_true = (const int*)d_in[1];
        y_pred = (const float*)d_in[0];
    }
    cudaFuncSetAttribute(ctc_fwd_kernel,
                         cudaFuncAttributeMaxDynamicSharedMemorySize, SMEM_TOTAL);
    ctc_fwd_kernel<<<Bn, 32, SMEM_TOTAL>>>(y_true, y_pred, (float*)d_out);
}